// round 1
// baseline (speedup 1.0000x reference)
#include <cuda_runtime.h>
#include <math.h>

// ---------------- problem constants ----------------
constexpr int B_  = 8;
constexpr int NN  = 2000;
constexpr int E_  = 512;
constexpr int HEN = 1024;
constexpr int D_  = 128;   // 2*IB
constexpr int HD  = 512;
constexpr int KF  = 4096;  // P*HD
constexpr int IB_ = 64;
constexpr long long MR = (long long)B_ * NN; // 16000 rows

// ---------------- scratch layout (single __device__ arena) ----------------
constexpr long long SZ_AG   = MR * E_;
constexpr long long SZ_HENC = MR * HEN;
constexpr long long SZ_H    = MR * D_;
constexpr long long SZ_GLW  = (long long)D_ * KF;
constexpr long long SZ_F    = MR * KF;
constexpr long long SZ_ATT  = (long long)B_ * NN * NN;
constexpr long long SZ_DINV = MR;
constexpr long long SZ_T    = MR * HD;
constexpr long long SZ_O    = MR * HD;
constexpr long long SZ_O3   = MR * D_;
constexpr long long SZ_Z    = (long long)B_ * IB_;

constexpr long long OFF_AG   = 0;
constexpr long long OFF_HENC = OFF_AG + SZ_AG;
constexpr long long OFF_H1   = OFF_HENC + SZ_HENC;
constexpr long long OFF_H2   = OFF_H1 + SZ_H;
constexpr long long OFF_GLW  = OFF_H2 + SZ_H;
constexpr long long OFF_F    = OFF_GLW + SZ_GLW;
constexpr long long OFF_ATT  = OFF_F + SZ_F;
constexpr long long OFF_DINV = OFF_ATT + SZ_ATT;
constexpr long long OFF_T    = OFF_DINV + SZ_DINV;
constexpr long long OFF_O1   = OFF_T + SZ_T;
constexpr long long OFF_O2   = OFF_O1 + SZ_O;
constexpr long long OFF_O3   = OFF_O2 + SZ_O;
constexpr long long OFF_Z    = OFF_O3 + SZ_O3;
constexpr long long SCRATCH_TOTAL = OFF_Z + SZ_Z;  // ~153.4M floats ~613 MB

__device__ float g_scratch[SCRATCH_TOTAL];

// ---------------- generic tiled SGEMM ----------------
// C[M,N] = act( epi( alpha * op(A) @ op(B) ) + bias )
// TA=0: A[m,k] row-major (lda=K stride). TA=1: A[k,m] (lda = M stride) -> computes A^T @ B.
// TB=0: B[k,n]. TB=1: B[n,k] -> computes A @ B^T.
// ACT: 0 none, 1 relu, 2 gelu(exact)
// EPI: 0 none, 1: v = dinv[m]*v (no bias expected), 2: v = dinv[m]*(v + Tm[m,n]) + bias (GCN aggregate)
template<int TA, int TB, int ACT, int EPI>
__global__ void __launch_bounds__(256, 2) sgemm_k(
    int M, int N, int K, float alpha,
    const float* __restrict__ A, int lda, long long sA,
    const float* __restrict__ B, int ldb, long long sB,
    float* __restrict__ C, int ldc, long long sC,
    const float* __restrict__ bias,
    const float* __restrict__ dinv, long long sD,
    const float* __restrict__ Tm, int ldt, long long sT)
{
    __shared__ float As[16][128];
    __shared__ float Bs[16][128];

    const int bz = blockIdx.z;
    A += bz * sA; B += bz * sB; C += bz * sC;
    if (EPI)      dinv += bz * sD;
    if (EPI == 2) Tm   += bz * sT;

    const int m0 = blockIdx.y * 128;
    const int n0 = blockIdx.x * 128;
    const int tid = threadIdx.x;
    const int ty = tid >> 4, tx = tid & 15;

    float acc[8][8];
#pragma unroll
    for (int i = 0; i < 8; i++)
#pragma unroll
        for (int j = 0; j < 8; j++) acc[i][j] = 0.f;

    for (int k0 = 0; k0 < K; k0 += 16) {
        // ---- load A tile -> As[k][m]
#pragma unroll
        for (int it = 0; it < 2; it++) {
            int v = tid + it * 256;
            if (TA == 0) {
                int row = v >> 2, kc = (v & 3) * 4;
                int gm = m0 + row;
                float4 val = make_float4(0.f, 0.f, 0.f, 0.f);
                if (gm < M) val = *reinterpret_cast<const float4*>(A + (long long)gm * lda + k0 + kc);
                As[kc + 0][row] = val.x; As[kc + 1][row] = val.y;
                As[kc + 2][row] = val.z; As[kc + 3][row] = val.w;
            } else {
                int kr = v >> 5, mc = (v & 31) * 4;
                int gm = m0 + mc;
                float4 val = make_float4(0.f, 0.f, 0.f, 0.f);
                const float* src = A + (long long)(k0 + kr) * lda + gm;
                if (gm + 3 < M) {
                    val = *reinterpret_cast<const float4*>(src);
                } else {
                    float t[4] = {0.f, 0.f, 0.f, 0.f};
                    for (int j = 0; j < 4; j++) if (gm + j < M) t[j] = src[j];
                    val = make_float4(t[0], t[1], t[2], t[3]);
                }
                *reinterpret_cast<float4*>(&As[kr][mc]) = val;
            }
        }
        // ---- load B tile -> Bs[k][n]
#pragma unroll
        for (int it = 0; it < 2; it++) {
            int v = tid + it * 256;
            if (TB == 0) {
                int kr = v >> 5, nc = (v & 31) * 4;
                int gn = n0 + nc;
                float4 val = make_float4(0.f, 0.f, 0.f, 0.f);
                const float* src = B + (long long)(k0 + kr) * ldb + gn;
                if (gn + 3 < N) {
                    val = *reinterpret_cast<const float4*>(src);
                } else {
                    float t[4] = {0.f, 0.f, 0.f, 0.f};
                    for (int j = 0; j < 4; j++) if (gn + j < N) t[j] = src[j];
                    val = make_float4(t[0], t[1], t[2], t[3]);
                }
                *reinterpret_cast<float4*>(&Bs[kr][nc]) = val;
            } else {
                int row = v >> 2, kc = (v & 3) * 4;
                int gn = n0 + row;
                float4 val = make_float4(0.f, 0.f, 0.f, 0.f);
                if (gn < N) val = *reinterpret_cast<const float4*>(B + (long long)gn * ldb + k0 + kc);
                Bs[kc + 0][row] = val.x; Bs[kc + 1][row] = val.y;
                Bs[kc + 2][row] = val.z; Bs[kc + 3][row] = val.w;
            }
        }
        __syncthreads();

#pragma unroll
        for (int kk = 0; kk < 16; kk++) {
            float ra[8], rb[8];
            *reinterpret_cast<float4*>(ra)     = *reinterpret_cast<const float4*>(&As[kk][ty * 8]);
            *reinterpret_cast<float4*>(ra + 4) = *reinterpret_cast<const float4*>(&As[kk][ty * 8 + 4]);
            *reinterpret_cast<float4*>(rb)     = *reinterpret_cast<const float4*>(&Bs[kk][tx * 8]);
            *reinterpret_cast<float4*>(rb + 4) = *reinterpret_cast<const float4*>(&Bs[kk][tx * 8 + 4]);
#pragma unroll
            for (int i = 0; i < 8; i++)
#pragma unroll
                for (int j = 0; j < 8; j++)
                    acc[i][j] = fmaf(ra[i], rb[j], acc[i][j]);
        }
        __syncthreads();
    }

    // ---- epilogue
#pragma unroll
    for (int i = 0; i < 8; i++) {
        int gm = m0 + ty * 8 + i;
        if (gm >= M) continue;
        float dv = 1.f;
        if (EPI) dv = dinv[gm];
#pragma unroll
        for (int j = 0; j < 8; j++) {
            int gn = n0 + tx * 8 + j;
            if (gn >= N) continue;
            float v = alpha * acc[i][j];
            if (EPI == 1) v = dv * v;
            if (EPI == 2) v = dv * (v + Tm[(long long)gm * ldt + gn]);
            if (bias)     v += bias[gn];
            if (ACT == 1) v = fmaxf(v, 0.f);
            if (ACT == 2) v = 0.5f * v * (1.f + erff(v * 0.70710678118654752f));
            C[(long long)gm * ldc + gn] = v;
        }
    }
}

// ---------------- A-matrix builder: Ag[r,e] = sigmoid(x[r]*gw[e]+gb[e]) * emb[r%N, e]
__global__ void build_ag_k(const float* __restrict__ x, const float* __restrict__ emb,
                           const float* __restrict__ gw, const float* __restrict__ gb,
                           float* __restrict__ Ag)
{
    long long idx = (long long)blockIdx.x * blockDim.x + threadIdx.x;
    if (idx >= MR * E_) return;
    int e = (int)(idx & (E_ - 1));
    long long rn = idx >> 9;           // E_=512
    int n = (int)(rn % NN);
    float t = fmaf(x[rn], gw[e], gb[e]);
    float sgm = 1.0f / (1.0f + expf(-t));
    Ag[idx] = sgm * emb[(long long)n * E_ + e];
}

// ---------------- concat gl_w [P,D,HD] -> GLW [D, P*HD]
__global__ void build_glw_k(const float* __restrict__ glw, float* __restrict__ GLW)
{
    int idx = blockIdx.x * blockDim.x + threadIdx.x;
    if (idx >= D_ * KF) return;
    int k = idx / KF, c = idx % KF;
    int p = c >> 9, hh = c & 511;      // HD=512
    GLW[idx] = glw[((long long)p * D_ + k) * HD + hh];
}

// ---------------- per-row top-k(50) threshold (exact radix select on float bits) + masked softmax, in place
__global__ void __launch_bounds__(256) topk_softmax_k(float* __restrict__ att)
{
    __shared__ float s[2000];
    __shared__ float wredf[8];
    __shared__ int   wredi[8];
    __shared__ float s_bcast;
    __shared__ int   s_cnt;

    long long row = blockIdx.x;
    float* r = att + row * 2000;
    int tid = threadIdx.x;
    int lane = tid & 31, wid = tid >> 5;

    for (int i = tid; i < 2000; i += 256) s[i] = r[i];
    __syncthreads();

    // row max (values are >= 0)
    float mx = 0.f;
    for (int i = tid; i < 2000; i += 256) mx = fmaxf(mx, s[i]);
#pragma unroll
    for (int o = 16; o; o >>= 1) mx = fmaxf(mx, __shfl_xor_sync(0xffffffffu, mx, o));
    if (lane == 0) wredf[wid] = mx;
    __syncthreads();
    if (tid == 0) { float m = wredf[0]; for (int w = 1; w < 8; w++) m = fmaxf(m, wredf[w]); s_bcast = m; }
    __syncthreads();
    mx = s_bcast;

    // radix select: largest u with count(bits >= u) >= 50  == bits of the 50th largest value
    unsigned prefix = 0u;
    for (int bit = 30; bit >= 0; bit--) {     // sign bit always 0 (att >= 0)
        unsigned cand = prefix | (1u << bit);
        int c = 0;
        for (int i = tid; i < 2000; i += 256) c += (__float_as_uint(s[i]) >= cand);
#pragma unroll
        for (int o = 16; o; o >>= 1) c += __shfl_xor_sync(0xffffffffu, c, o);
        if (lane == 0) wredi[wid] = c;
        __syncthreads();
        if (tid == 0) { int t = 0; for (int w = 0; w < 8; w++) t += wredi[w]; s_cnt = t; }
        __syncthreads();
        if (s_cnt >= 50) prefix = cand;
        __syncthreads();
    }
    float thr = __uint_as_float(prefix);

    // masked softmax; masked entries are exactly 0 (expf(-1e9 - mx) == 0)
    float sum = 0.f;
    for (int i = tid; i < 2000; i += 256) {
        float v = s[i];
        float e = (v >= thr) ? expf(v - mx) : 0.f;
        s[i] = e; sum += e;
    }
#pragma unroll
    for (int o = 16; o; o >>= 1) sum += __shfl_xor_sync(0xffffffffu, sum, o);
    if (lane == 0) wredf[wid] = sum;
    __syncthreads();
    if (tid == 0) { float t = 0.f; for (int w = 0; w < 8; w++) t += wredf[w]; s_bcast = t; }
    __syncthreads();
    float inv = 1.0f / s_bcast;
    for (int i = tid; i < 2000; i += 256) r[i] = s[i] * inv;
}

// ---------------- dinv[b,i] = 1/sqrt(1 + sum_j adj[b,j,i])
__global__ void colsum_k(const float* __restrict__ adj, float* __restrict__ dinv)
{
    int b = blockIdx.y;
    int i = blockIdx.x * blockDim.x + threadIdx.x;
    if (i >= 2000) return;
    const float* p = adj + (long long)b * 2000 * 2000 + i;
    float s0 = 0.f, s1 = 0.f, s2 = 0.f, s3 = 0.f;
    for (int j = 0; j < 2000; j += 4) {
        s0 += p[(long long)j * 2000];
        s1 += p[(long long)(j + 1) * 2000];
        s2 += p[(long long)(j + 2) * 2000];
        s3 += p[(long long)(j + 3) * 2000];
    }
    float d = 1.0f + ((s0 + s1) + (s2 + s3));
    dinv[b * 2000 + i] = 1.0f / sqrtf(d);
}

// ---------------- g = mean_i O3[b,i,:]; mu/std/z
__global__ void meanz_k(const float* __restrict__ O3, const float* __restrict__ eps,
                        float* __restrict__ mu, float* __restrict__ stdv, float* __restrict__ z)
{
    int b = blockIdx.x, d = threadIdx.x;  // 128 threads
    const float* p = O3 + ((long long)b * 2000) * 128 + d;
    float s0 = 0.f, s1 = 0.f, s2 = 0.f, s3 = 0.f;
    for (int i = 0; i < 2000; i += 4) {
        s0 += p[(long long)i * 128];
        s1 += p[(long long)(i + 1) * 128];
        s2 += p[(long long)(i + 2) * 128];
        s3 += p[(long long)(i + 3) * 128];
    }
    __shared__ float sg[128];
    sg[d] = ((s0 + s1) + (s2 + s3)) / 2000.0f;
    __syncthreads();
    if (d < 64) {
        float m = sg[d];
        float sp = log1pf(expf(sg[64 + d] - 64.0f));
        mu[b * 64 + d] = m;
        stdv[b * 64 + d] = sp;
        z[b * 64 + d] = fmaf(eps[b * 64 + d], sp, m);
    }
}

// ---------------- decoder: relu( relu( (z@w1+b1)*(g/sqrt(1+1e-5))+be ) @ w2 + b2 )
__global__ void __launch_bounds__(256) decode_k(
    const float* __restrict__ z, const float* __restrict__ w1, const float* __restrict__ b1,
    const float* __restrict__ gamma, const float* __restrict__ beta,
    const float* __restrict__ w2, const float* __restrict__ b2,
    float* __restrict__ xrec)
{
    __shared__ float h[1024];
    __shared__ float zs[64];
    int b = blockIdx.x, tid = threadIdx.x;
    if (tid < 64) zs[tid] = z[b * 64 + tid];
    __syncthreads();
    const float invc = 1.0f / sqrtf(1.0f + 1e-5f);
    for (int c = tid; c < 1024; c += 256) {
        float a = b1[c];
#pragma unroll 8
        for (int k = 0; k < 64; k++) a = fmaf(zs[k], w1[k * 1024 + c], a);
        a = a * (gamma[c] * invc) + beta[c];
        h[c] = fmaxf(a, 0.f);
    }
    __syncthreads();
    for (int c = tid; c < 2000; c += 256) {
        float a = b2[c];
        for (int k = 0; k < 1024; k++) a = fmaf(h[k], w2[k * 2000 + c], a);
        xrec[b * 2000 + c] = fmaxf(a, 0.f);
    }
}

// ---------------- host orchestration ----------------
extern "C" void kernel_launch(void* const* d_in, const int* in_sizes, int n_in,
                              void* d_out, int out_size)
{
    const float* x1     = (const float*)d_in[0];
    const float* x2     = (const float*)d_in[1];
    const float* emb1   = (const float*)d_in[2];
    const float* gate_w = (const float*)d_in[3];
    const float* gate_b = (const float*)d_in[4];
    const float* enc_w1 = (const float*)d_in[5];
    const float* enc_b1 = (const float*)d_in[6];
    const float* enc_w2 = (const float*)d_in[7];
    const float* enc_b2 = (const float*)d_in[8];
    const float* gl_w   = (const float*)d_in[9];
    const float* g_w1   = (const float*)d_in[10];
    const float* g_b1   = (const float*)d_in[11];
    const float* g_w2   = (const float*)d_in[12];
    const float* g_b2   = (const float*)d_in[13];
    const float* g_w3   = (const float*)d_in[14];
    const float* g_b3   = (const float*)d_in[15];
    const float* dW1[2] = {(const float*)d_in[16], (const float*)d_in[22]};
    const float* dB1[2] = {(const float*)d_in[17], (const float*)d_in[23]};
    const float* dG [2] = {(const float*)d_in[18], (const float*)d_in[24]};
    const float* dBe[2] = {(const float*)d_in[19], (const float*)d_in[25]};
    const float* dW2[2] = {(const float*)d_in[20], (const float*)d_in[26]};
    const float* dB2[2] = {(const float*)d_in[21], (const float*)d_in[27]};
    const float* epsA[2]= {(const float*)d_in[28], (const float*)d_in[29]};

    float* sc = nullptr;
    cudaGetSymbolAddress((void**)&sc, g_scratch);
    float* Ag   = sc + OFF_AG;
    float* Henc = sc + OFF_HENC;
    float* Hbuf[2] = {sc + OFF_H1, sc + OFF_H2};
    float* GLW  = sc + OFF_GLW;
    float* F    = sc + OFF_F;
    float* att  = sc + OFF_ATT;
    float* dinv = sc + OFF_DINV;
    float* T    = sc + OFF_T;
    float* O1   = sc + OFF_O1;
    float* O2   = sc + OFF_O2;
    float* O3   = sc + OFF_O3;
    float* zb   = sc + OFF_Z;

    float* out = (float*)d_out;
    float* xrec[2] = {out,          out + 16000};
    float* muo [2] = {out + 32000,  out + 33024};
    float* stdo[2] = {out + 32512,  out + 33536};

    build_glw_k<<<(D_ * KF + 255) / 256, 256>>>(gl_w, GLW);

    // ---- encoders (x1, x2) ----
    for (int xi = 0; xi < 2; xi++) {
        const float* x = xi ? x2 : x1;
        long long tot = MR * E_;
        build_ag_k<<<(unsigned)((tot + 255) / 256), 256>>>(x, emb1, gate_w, gate_b, Ag);
        // Henc = gelu(Ag @ enc_w1 + b1)  [16000,1024]
        sgemm_k<0,0,2,0><<<dim3(HEN / 128, 125, 1), 256>>>(
            16000, HEN, E_, 1.f, Ag, E_, 0, enc_w1, HEN, 0, Henc, HEN, 0,
            enc_b1, nullptr, 0, nullptr, 0, 0);
        // H = Henc @ enc_w2 + b2  [16000,128]
        sgemm_k<0,0,0,0><<<dim3(1, 125, 1), 256>>>(
            16000, D_, HEN, 1.f, Henc, HEN, 0, enc_w2, D_, 0, Hbuf[xi], D_, 0,
            enc_b2, nullptr, 0, nullptr, 0, 0);
    }

    // ---- per-view: adjacency learning + GCN + VIB head + decoder ----
    for (int xi = 0; xi < 2; xi++) {
        float* H = Hbuf[xi];
        // F = relu(H @ GLW)  [16000,4096]
        sgemm_k<0,0,1,0><<<dim3(KF / 128, 125, 1), 256>>>(
            16000, KF, D_, 1.f, H, D_, 0, GLW, KF, 0, F, KF, 0,
            nullptr, nullptr, 0, nullptr, 0, 0);
        // att[b] = F_b @ F_b^T / 8   [8,2000,2000]
        sgemm_k<0,1,0,0><<<dim3(16, 16, 8), 256>>>(
            2000, 2000, KF, 0.125f,
            F, KF, (long long)2000 * KF,
            F, KF, (long long)2000 * KF,
            att, 2000, (long long)2000 * 2000,
            nullptr, nullptr, 0, nullptr, 0, 0);
        // top-k threshold + masked softmax (in place)
        topk_softmax_k<<<16000, 256>>>(att);
        // dinv
        colsum_k<<<dim3(8, 8), 256>>>(att, dinv);

        // GCN layer 1: T = dinv ⊙ (H @ g_w1); O1 = relu(dinv[i]*((adjᵀT)+T) + b1)
        sgemm_k<0,0,0,1><<<dim3(HD / 128, 125, 1), 256>>>(
            16000, HD, D_, 1.f, H, D_, 0, g_w1, HD, 0, T, HD, 0,
            nullptr, dinv, 0, nullptr, 0, 0);
        sgemm_k<1,0,1,2><<<dim3(HD / 128, 16, 8), 256>>>(
            2000, HD, 2000, 1.f,
            att, 2000, (long long)2000 * 2000,
            T, HD, (long long)2000 * HD,
            O1, HD, (long long)2000 * HD,
            g_b1, dinv, 2000, T, HD, (long long)2000 * HD);
        // layer 2
        sgemm_k<0,0,0,1><<<dim3(HD / 128, 125, 1), 256>>>(
            16000, HD, HD, 1.f, O1, HD, 0, g_w2, HD, 0, T, HD, 0,
            nullptr, dinv, 0, nullptr, 0, 0);
        sgemm_k<1,0,1,2><<<dim3(HD / 128, 16, 8), 256>>>(
            2000, HD, 2000, 1.f,
            att, 2000, (long long)2000 * 2000,
            T, HD, (long long)2000 * HD,
            O2, HD, (long long)2000 * HD,
            g_b2, dinv, 2000, T, HD, (long long)2000 * HD);
        // layer 3 (no relu)
        sgemm_k<0,0,0,1><<<dim3(1, 125, 1), 256>>>(
            16000, D_, HD, 1.f, O2, HD, 0, g_w3, D_, 0, T, D_, 0,
            nullptr, dinv, 0, nullptr, 0, 0);
        sgemm_k<1,0,0,2><<<dim3(1, 16, 8), 256>>>(
            2000, D_, 2000, 1.f,
            att, 2000, (long long)2000 * 2000,
            T, D_, (long long)2000 * D_,
            O3, D_, (long long)2000 * D_,
            g_b3, dinv, 2000, T, D_, (long long)2000 * D_);

        // VIB head + decode
        meanz_k<<<8, 128>>>(O3, epsA[xi], muo[xi], stdo[xi], zb);
        decode_k<<<8, 256>>>(zb, dW1[xi], dB1[xi], dG[xi], dBe[xi], dW2[xi], dB2[xi], xrec[xi]);
    }
}

// round 2
// speedup vs baseline: 2.1290x; 2.1290x over previous
#include <cuda_runtime.h>
#include <math.h>
#include <stdint.h>

// ---------------- problem constants ----------------
constexpr int B_  = 8;
constexpr int NN  = 2000;
constexpr int E_  = 512;
constexpr int HEN = 1024;
constexpr int D_  = 128;   // 2*IB
constexpr int HD  = 512;
constexpr int KF  = 4096;  // P*HD
constexpr int IB_ = 64;
constexpr long long MR = (long long)B_ * NN; // 16000 rows

// ---------------- scratch layout ----------------
constexpr long long SZ_AG   = MR * E_;
constexpr long long SZ_HENC = MR * HEN;
constexpr long long SZ_H    = MR * D_;
constexpr long long SZ_GLW  = (long long)D_ * KF;
constexpr long long SZ_F    = MR * KF;
constexpr long long SZ_ATT  = (long long)B_ * NN * NN;
constexpr long long SZ_DINV = MR;
constexpr long long SZ_T    = MR * HD;
constexpr long long SZ_O    = MR * HD;
constexpr long long SZ_O3   = MR * D_;
constexpr long long SZ_Z    = (long long)B_ * IB_;

constexpr long long OFF_AG   = 0;
constexpr long long OFF_HENC = OFF_AG + SZ_AG;
constexpr long long OFF_H1   = OFF_HENC + SZ_HENC;
constexpr long long OFF_H2   = OFF_H1 + SZ_H;
constexpr long long OFF_GLW  = OFF_H2 + SZ_H;
constexpr long long OFF_F    = OFF_GLW + SZ_GLW;
constexpr long long OFF_ATT  = OFF_F + SZ_F;
constexpr long long OFF_DINV = OFF_ATT + SZ_ATT;
constexpr long long OFF_T    = OFF_DINV + SZ_DINV;
constexpr long long OFF_O1   = OFF_T + SZ_T;
constexpr long long OFF_O2   = OFF_O1 + SZ_O;
constexpr long long OFF_O3   = OFF_O2 + SZ_O;
constexpr long long OFF_Z    = OFF_O3 + SZ_O3;
constexpr long long SCRATCH_TOTAL = OFF_Z + SZ_Z;

__device__ float g_scratch[SCRATCH_TOTAL];

// ---------------- tf32 helpers ----------------
__device__ __forceinline__ uint32_t f2tf32(float v) {
    uint32_t r;
    asm("cvt.rna.tf32.f32 %0, %1;" : "=r"(r) : "f"(v));
    return r;
}

__device__ __forceinline__ void mma_tf32(float* c, const uint32_t* a, uint32_t b0, uint32_t b1) {
    asm volatile(
        "mma.sync.aligned.m16n8k8.row.col.f32.tf32.tf32.f32 "
        "{%0,%1,%2,%3}, {%4,%5,%6,%7}, {%8,%9}, {%0,%1,%2,%3};"
        : "+f"(c[0]), "+f"(c[1]), "+f"(c[2]), "+f"(c[3])
        : "r"(a[0]), "r"(a[1]), "r"(a[2]), "r"(a[3]), "r"(b0), "r"(b1));
}

// ---------------- tf32 tensor-core GEMM ----------------
// C[M,N] = act( epi( alpha * op(A) @ op(B) ) + bias )
// TA=0: A[m,k] (lda=K-ish). TA=1: A[k,m] -> A^T @ B.
// TB=0: B[k,n]. TB=1: B[n,k] -> A @ B^T.
// ACT: 0 none, 1 relu, 2 gelu(exact)
// EPI: 0 none, 1: v = dinv[m]*v, 2: v = dinv[m]*(v + Tm[m,n]) + bias (GCN aggregate)
// SYM: gram symmetry — compute bm<=bn only, mirror-write the off-diagonal tiles.
// Block: 128x128 tile, k-tile 16, 256 threads = 8 warps (4 m x 2 n), warp tile 32x64.
template<int TA, int TB, int ACT, int EPI, int SYM>
__global__ void __launch_bounds__(256, 2) tgemm_k(
    int M, int N, int K, float alpha,
    const float* __restrict__ A, int lda, long long sA,
    const float* __restrict__ B, int ldb, long long sB,
    float* __restrict__ C, int ldc, long long sC,
    const float* __restrict__ bias,
    const float* __restrict__ dinv, long long sD,
    const float* __restrict__ Tm, int ldt, long long sT)
{
    constexpr int PAD = 20;  // floats per smem row (16 + 4): conflict-free frag loads
    __shared__ uint32_t As[128 * PAD];
    __shared__ uint32_t Bs[128 * PAD];

    const int bz = blockIdx.z;
    A += bz * sA; B += bz * sB; C += bz * sC;
    if (EPI)      dinv += bz * sD;
    if (EPI == 2) Tm   += bz * sT;

    const int bn = blockIdx.x, bm = blockIdx.y;
    if (SYM && bm > bn) return;
    const int m0 = bm * 128, n0 = bn * 128;

    const int tid  = threadIdx.x;
    const int lane = tid & 31, warp = tid >> 5;
    const int g = lane >> 2, th = lane & 3;
    const int wm = (warp >> 1) * 32;
    const int wn = (warp & 1) * 64;

    float acc[2][8][4];
#pragma unroll
    for (int i = 0; i < 2; i++)
#pragma unroll
        for (int j = 0; j < 8; j++)
#pragma unroll
            for (int l = 0; l < 4; l++) acc[i][j][l] = 0.f;

    float ra[8], rb[8];
    const int KT = K >> 4;

    // ---- tile load into registers (A) ----
    auto loadA = [&](int kt) {
#pragma unroll
        for (int it = 0; it < 2; it++) {
            int c = tid * 2 + it;
            if (TA == 0) {
                int row = c >> 2, kc = (c & 3) * 4;
                int gm = m0 + row;
                float4 v = make_float4(0.f, 0.f, 0.f, 0.f);
                if (gm < M) v = *reinterpret_cast<const float4*>(A + (long long)gm * lda + kt * 16 + kc);
                ra[it*4+0]=v.x; ra[it*4+1]=v.y; ra[it*4+2]=v.z; ra[it*4+3]=v.w;
            } else {
                int kr = c >> 5, mc = (c & 31) * 4;
                int gm = m0 + mc;
                float4 v = make_float4(0.f, 0.f, 0.f, 0.f);
                const float* src = A + (long long)(kt * 16 + kr) * lda + gm;
                if (gm + 3 < M) v = *reinterpret_cast<const float4*>(src);
                else { float t[4]={0,0,0,0}; for (int j=0;j<4;j++) if (gm+j<M) t[j]=src[j]; v=make_float4(t[0],t[1],t[2],t[3]); }
                ra[it*4+0]=v.x; ra[it*4+1]=v.y; ra[it*4+2]=v.z; ra[it*4+3]=v.w;
            }
        }
    };
    auto loadB = [&](int kt) {
#pragma unroll
        for (int it = 0; it < 2; it++) {
            int c = tid * 2 + it;
            if (TB == 1) {
                int row = c >> 2, kc = (c & 3) * 4;
                int gn = n0 + row;
                float4 v = make_float4(0.f, 0.f, 0.f, 0.f);
                if (gn < N) v = *reinterpret_cast<const float4*>(B + (long long)gn * ldb + kt * 16 + kc);
                rb[it*4+0]=v.x; rb[it*4+1]=v.y; rb[it*4+2]=v.z; rb[it*4+3]=v.w;
            } else {
                int kr = c >> 5, nc = (c & 31) * 4;
                int gn = n0 + nc;
                float4 v = make_float4(0.f, 0.f, 0.f, 0.f);
                const float* src = B + (long long)(kt * 16 + kr) * ldb + gn;
                if (gn + 3 < N) v = *reinterpret_cast<const float4*>(src);
                else { float t[4]={0,0,0,0}; for (int j=0;j<4;j++) if (gn+j<N) t[j]=src[j]; v=make_float4(t[0],t[1],t[2],t[3]); }
                rb[it*4+0]=v.x; rb[it*4+1]=v.y; rb[it*4+2]=v.z; rb[it*4+3]=v.w;
            }
        }
    };
    auto stsA = [&]() {
#pragma unroll
        for (int it = 0; it < 2; it++) {
            int c = tid * 2 + it;
            if (TA == 0) {
                int row = c >> 2, kc = (c & 3) * 4;
#pragma unroll
                for (int j = 0; j < 4; j++) As[row * PAD + kc + j] = f2tf32(ra[it*4+j]);
            } else {
                int kr = c >> 5, mc = (c & 31) * 4;
#pragma unroll
                for (int j = 0; j < 4; j++) As[(mc + j) * PAD + kr] = f2tf32(ra[it*4+j]);
            }
        }
    };
    auto stsB = [&]() {
#pragma unroll
        for (int it = 0; it < 2; it++) {
            int c = tid * 2 + it;
            if (TB == 1) {
                int row = c >> 2, kc = (c & 3) * 4;
#pragma unroll
                for (int j = 0; j < 4; j++) Bs[row * PAD + kc + j] = f2tf32(rb[it*4+j]);
            } else {
                int kr = c >> 5, nc = (c & 31) * 4;
#pragma unroll
                for (int j = 0; j < 4; j++) Bs[(nc + j) * PAD + kr] = f2tf32(rb[it*4+j]);
            }
        }
    };

    loadA(0); loadB(0);
    for (int kt = 0; kt < KT; kt++) {
        stsA(); stsB();
        __syncthreads();
        if (kt + 1 < KT) { loadA(kt + 1); loadB(kt + 1); }
#pragma unroll
        for (int s = 0; s < 2; s++) {
            const int k0 = s * 8;
            uint32_t a[2][4];
#pragma unroll
            for (int mt = 0; mt < 2; mt++) {
                int mrow = wm + mt * 16 + g;
                a[mt][0] = As[mrow * PAD + k0 + th];
                a[mt][1] = As[(mrow + 8) * PAD + k0 + th];
                a[mt][2] = As[mrow * PAD + k0 + th + 4];
                a[mt][3] = As[(mrow + 8) * PAD + k0 + th + 4];
            }
#pragma unroll
            for (int nt = 0; nt < 8; nt++) {
                int nrow = wn + nt * 8 + g;
                uint32_t b0 = Bs[nrow * PAD + k0 + th];
                uint32_t b1 = Bs[nrow * PAD + k0 + th + 4];
                mma_tf32(acc[0][nt], a[0], b0, b1);
                mma_tf32(acc[1][nt], a[1], b0, b1);
            }
        }
        __syncthreads();
    }

    // ---- epilogue ----
#pragma unroll
    for (int mt = 0; mt < 2; mt++) {
#pragma unroll
        for (int nt = 0; nt < 8; nt++) {
#pragma unroll
            for (int e = 0; e < 4; e++) {
                int gm = m0 + wm + mt * 16 + g + (e >= 2 ? 8 : 0);
                int gn = n0 + wn + nt * 8 + 2 * th + (e & 1);
                if (gm >= M || gn >= N) continue;
                float v = alpha * acc[mt][nt][e];
                if (EPI == 1) v = dinv[gm] * v;
                if (EPI == 2) v = dinv[gm] * (v + Tm[(long long)gm * ldt + gn]);
                if (bias)     v += bias[gn];
                if (ACT == 1) v = fmaxf(v, 0.f);
                if (ACT == 2) v = 0.5f * v * (1.f + erff(v * 0.70710678118654752f));
                C[(long long)gm * ldc + gn] = v;
                if (SYM && bm < bn) C[(long long)gn * ldc + gm] = v;
            }
        }
    }
}

// ---------------- A-matrix builder ----------------
__global__ void build_ag_k(const float* __restrict__ x, const float* __restrict__ emb,
                           const float* __restrict__ gw, const float* __restrict__ gb,
                           float* __restrict__ Ag)
{
    long long idx = (long long)blockIdx.x * blockDim.x + threadIdx.x;
    if (idx >= MR * E_) return;
    int e = (int)(idx & (E_ - 1));
    long long rn = idx >> 9;
    int n = (int)(rn % NN);
    float t = fmaf(x[rn], gw[e], gb[e]);
    float sgm = 1.0f / (1.0f + expf(-t));
    Ag[idx] = sgm * emb[(long long)n * E_ + e];
}

// ---------------- concat gl_w [P,D,HD] -> GLW [D, P*HD] ----------------
__global__ void build_glw_k(const float* __restrict__ glw, float* __restrict__ GLW)
{
    int idx = blockIdx.x * blockDim.x + threadIdx.x;
    if (idx >= D_ * KF) return;
    int k = idx / KF, c = idx % KF;
    int p = c >> 9, hh = c & 511;
    GLW[idx] = glw[((long long)p * D_ + k) * HD + hh];
}

// ---------------- top-k(50) threshold + masked softmax, in place ----------------
__global__ void __launch_bounds__(256) topk_softmax_k(float* __restrict__ att)
{
    __shared__ float s[2000];
    __shared__ float wredf[8];
    __shared__ int   wredi[8];
    __shared__ float s_bcast;
    __shared__ int   s_cnt;

    long long row = blockIdx.x;
    float* r = att + row * 2000;
    int tid = threadIdx.x;
    int lane = tid & 31, wid = tid >> 5;

    for (int i = tid; i < 2000; i += 256) s[i] = r[i];
    __syncthreads();

    float mx = 0.f;
    for (int i = tid; i < 2000; i += 256) mx = fmaxf(mx, s[i]);
#pragma unroll
    for (int o = 16; o; o >>= 1) mx = fmaxf(mx, __shfl_xor_sync(0xffffffffu, mx, o));
    if (lane == 0) wredf[wid] = mx;
    __syncthreads();
    if (tid == 0) { float m = wredf[0]; for (int w = 1; w < 8; w++) m = fmaxf(m, wredf[w]); s_bcast = m; }
    __syncthreads();
    mx = s_bcast;

    unsigned prefix = 0u;
    for (int bit = 30; bit >= 0; bit--) {
        unsigned cand = prefix | (1u << bit);
        int c = 0;
        for (int i = tid; i < 2000; i += 256) c += (__float_as_uint(s[i]) >= cand);
#pragma unroll
        for (int o = 16; o; o >>= 1) c += __shfl_xor_sync(0xffffffffu, c, o);
        if (lane == 0) wredi[wid] = c;
        __syncthreads();
        if (tid == 0) { int t = 0; for (int w = 0; w < 8; w++) t += wredi[w]; s_cnt = t; }
        __syncthreads();
        if (s_cnt >= 50) prefix = cand;
        __syncthreads();
    }
    float thr = __uint_as_float(prefix);

    float sum = 0.f;
    for (int i = tid; i < 2000; i += 256) {
        float v = s[i];
        float e = (v >= thr) ? expf(v - mx) : 0.f;
        s[i] = e; sum += e;
    }
#pragma unroll
    for (int o = 16; o; o >>= 1) sum += __shfl_xor_sync(0xffffffffu, sum, o);
    if (lane == 0) wredf[wid] = sum;
    __syncthreads();
    if (tid == 0) { float t = 0.f; for (int w = 0; w < 8; w++) t += wredf[w]; s_bcast = t; }
    __syncthreads();
    float inv = 1.0f / s_bcast;
    for (int i = tid; i < 2000; i += 256) r[i] = s[i] * inv;
}

// ---------------- dinv[b,i] = 1/sqrt(1 + sum_j adj[b,j,i]) ----------------
__global__ void colsum_k(const float* __restrict__ adj, float* __restrict__ dinv)
{
    int b = blockIdx.y;
    int i = blockIdx.x * blockDim.x + threadIdx.x;
    if (i >= 2000) return;
    const float* p = adj + (long long)b * 2000 * 2000 + i;
    float s0 = 0.f, s1 = 0.f, s2 = 0.f, s3 = 0.f;
    for (int j = 0; j < 2000; j += 4) {
        s0 += p[(long long)j * 2000];
        s1 += p[(long long)(j + 1) * 2000];
        s2 += p[(long long)(j + 2) * 2000];
        s3 += p[(long long)(j + 3) * 2000];
    }
    float d = 1.0f + ((s0 + s1) + (s2 + s3));
    dinv[b * 2000 + i] = 1.0f / sqrtf(d);
}

// ---------------- mean over nodes; mu/std/z ----------------
__global__ void meanz_k(const float* __restrict__ O3, const float* __restrict__ eps,
                        float* __restrict__ mu, float* __restrict__ stdv, float* __restrict__ z)
{
    int b = blockIdx.x, d = threadIdx.x;
    const float* p = O3 + ((long long)b * 2000) * 128 + d;
    float s0 = 0.f, s1 = 0.f, s2 = 0.f, s3 = 0.f;
    for (int i = 0; i < 2000; i += 4) {
        s0 += p[(long long)i * 128];
        s1 += p[(long long)(i + 1) * 128];
        s2 += p[(long long)(i + 2) * 128];
        s3 += p[(long long)(i + 3) * 128];
    }
    __shared__ float sg[128];
    sg[d] = ((s0 + s1) + (s2 + s3)) / 2000.0f;
    __syncthreads();
    if (d < 64) {
        float m = sg[d];
        float sp = log1pf(expf(sg[64 + d] - 64.0f));
        mu[b * 64 + d] = m;
        stdv[b * 64 + d] = sp;
        z[b * 64 + d] = fmaf(eps[b * 64 + d], sp, m);
    }
}

// ---------------- decoder ----------------
__global__ void __launch_bounds__(256) decode_k(
    const float* __restrict__ z, const float* __restrict__ w1, const float* __restrict__ b1,
    const float* __restrict__ gamma, const float* __restrict__ beta,
    const float* __restrict__ w2, const float* __restrict__ b2,
    float* __restrict__ xrec)
{
    __shared__ float h[1024];
    __shared__ float zs[64];
    int b = blockIdx.x, tid = threadIdx.x;
    if (tid < 64) zs[tid] = z[b * 64 + tid];
    __syncthreads();
    const float invc = 1.0f / sqrtf(1.0f + 1e-5f);
    for (int c = tid; c < 1024; c += 256) {
        float a = b1[c];
#pragma unroll 8
        for (int k = 0; k < 64; k++) a = fmaf(zs[k], w1[k * 1024 + c], a);
        a = a * (gamma[c] * invc) + beta[c];
        h[c] = fmaxf(a, 0.f);
    }
    __syncthreads();
    for (int c = tid; c < 2000; c += 256) {
        float a = b2[c];
        for (int k = 0; k < 1024; k++) a = fmaf(h[k], w2[k * 2000 + c], a);
        xrec[b * 2000 + c] = fmaxf(a, 0.f);
    }
}

// ---------------- host orchestration ----------------
extern "C" void kernel_launch(void* const* d_in, const int* in_sizes, int n_in,
                              void* d_out, int out_size)
{
    const float* x1     = (const float*)d_in[0];
    const float* x2     = (const float*)d_in[1];
    const float* emb1   = (const float*)d_in[2];
    const float* gate_w = (const float*)d_in[3];
    const float* gate_b = (const float*)d_in[4];
    const float* enc_w1 = (const float*)d_in[5];
    const float* enc_b1 = (const float*)d_in[6];
    const float* enc_w2 = (const float*)d_in[7];
    const float* enc_b2 = (const float*)d_in[8];
    const float* gl_w   = (const float*)d_in[9];
    const float* g_w1   = (const float*)d_in[10];
    const float* g_b1   = (const float*)d_in[11];
    const float* g_w2   = (const float*)d_in[12];
    const float* g_b2   = (const float*)d_in[13];
    const float* g_w3   = (const float*)d_in[14];
    const float* g_b3   = (const float*)d_in[15];
    const float* dW1[2] = {(const float*)d_in[16], (const float*)d_in[22]};
    const float* dB1[2] = {(const float*)d_in[17], (const float*)d_in[23]};
    const float* dG [2] = {(const float*)d_in[18], (const float*)d_in[24]};
    const float* dBe[2] = {(const float*)d_in[19], (const float*)d_in[25]};
    const float* dW2[2] = {(const float*)d_in[20], (const float*)d_in[26]};
    const float* dB2[2] = {(const float*)d_in[21], (const float*)d_in[27]};
    const float* epsA[2]= {(const float*)d_in[28], (const float*)d_in[29]};

    float* sc = nullptr;
    cudaGetSymbolAddress((void**)&sc, g_scratch);
    float* Ag   = sc + OFF_AG;
    float* Henc = sc + OFF_HENC;
    float* Hbuf[2] = {sc + OFF_H1, sc + OFF_H2};
    float* GLW  = sc + OFF_GLW;
    float* F    = sc + OFF_F;
    float* att  = sc + OFF_ATT;
    float* dinv = sc + OFF_DINV;
    float* T    = sc + OFF_T;
    float* O1   = sc + OFF_O1;
    float* O2   = sc + OFF_O2;
    float* O3   = sc + OFF_O3;
    float* zb   = sc + OFF_Z;

    float* out = (float*)d_out;
    float* xrec[2] = {out,          out + 16000};
    float* muo [2] = {out + 32000,  out + 33024};
    float* stdo[2] = {out + 32512,  out + 33536};

    build_glw_k<<<(D_ * KF + 255) / 256, 256>>>(gl_w, GLW);

    // ---- encoders ----
    for (int xi = 0; xi < 2; xi++) {
        const float* x = xi ? x2 : x1;
        long long tot = MR * E_;
        build_ag_k<<<(unsigned)((tot + 255) / 256), 256>>>(x, emb1, gate_w, gate_b, Ag);
        tgemm_k<0,0,2,0,0><<<dim3(HEN / 128, 125, 1), 256>>>(
            16000, HEN, E_, 1.f, Ag, E_, 0, enc_w1, HEN, 0, Henc, HEN, 0,
            enc_b1, nullptr, 0, nullptr, 0, 0);
        tgemm_k<0,0,0,0,0><<<dim3(1, 125, 1), 256>>>(
            16000, D_, HEN, 1.f, Henc, HEN, 0, enc_w2, D_, 0, Hbuf[xi], D_, 0,
            enc_b2, nullptr, 0, nullptr, 0, 0);
    }

    // ---- per-view ----
    for (int xi = 0; xi < 2; xi++) {
        float* H = Hbuf[xi];
        // F = relu(H @ GLW)
        tgemm_k<0,0,1,0,0><<<dim3(KF / 128, 125, 1), 256>>>(
            16000, KF, D_, 1.f, H, D_, 0, GLW, KF, 0, F, KF, 0,
            nullptr, nullptr, 0, nullptr, 0, 0);
        // att[b] = F_b @ F_b^T / 8  (symmetric: compute upper tiles, mirror)
        tgemm_k<0,1,0,0,1><<<dim3(16, 16, 8), 256>>>(
            2000, 2000, KF, 0.125f,
            F, KF, (long long)2000 * KF,
            F, KF, (long long)2000 * KF,
            att, 2000, (long long)2000 * 2000,
            nullptr, nullptr, 0, nullptr, 0, 0);
        topk_softmax_k<<<16000, 256>>>(att);
        colsum_k<<<dim3(8, 8), 256>>>(att, dinv);

        // GCN layer 1
        tgemm_k<0,0,0,1,0><<<dim3(HD / 128, 125, 1), 256>>>(
            16000, HD, D_, 1.f, H, D_, 0, g_w1, HD, 0, T, HD, 0,
            nullptr, dinv, 0, nullptr, 0, 0);
        tgemm_k<1,0,1,2,0><<<dim3(HD / 128, 16, 8), 256>>>(
            2000, HD, 2000, 1.f,
            att, 2000, (long long)2000 * 2000,
            T, HD, (long long)2000 * HD,
            O1, HD, (long long)2000 * HD,
            g_b1, dinv, 2000, T, HD, (long long)2000 * HD);
        // layer 2
        tgemm_k<0,0,0,1,0><<<dim3(HD / 128, 125, 1), 256>>>(
            16000, HD, HD, 1.f, O1, HD, 0, g_w2, HD, 0, T, HD, 0,
            nullptr, dinv, 0, nullptr, 0, 0);
        tgemm_k<1,0,1,2,0><<<dim3(HD / 128, 16, 8), 256>>>(
            2000, HD, 2000, 1.f,
            att, 2000, (long long)2000 * 2000,
            T, HD, (long long)2000 * HD,
            O2, HD, (long long)2000 * HD,
            g_b2, dinv, 2000, T, HD, (long long)2000 * HD);
        // layer 3 (no relu)
        tgemm_k<0,0,0,1,0><<<dim3(1, 125, 1), 256>>>(
            16000, D_, HD, 1.f, O2, HD, 0, g_w3, D_, 0, T, D_, 0,
            nullptr, dinv, 0, nullptr, 0, 0);
        tgemm_k<1,0,0,2,0><<<dim3(1, 16, 8), 256>>>(
            2000, D_, 2000, 1.f,
            att, 2000, (long long)2000 * 2000,
            T, D_, (long long)2000 * D_,
            O3, D_, (long long)2000 * D_,
            g_b3, dinv, 2000, T, D_, (long long)2000 * D_);

        meanz_k<<<8, 128>>>(O3, epsA[xi], muo[xi], stdo[xi], zb);
        decode_k<<<8, 256>>>(zb, dW1[xi], dB1[xi], dG[xi], dBe[xi], dW2[xi], dB2[xi], xrec[xi]);
    }
}

// round 3
// speedup vs baseline: 2.2511x; 1.0574x over previous
#include <cuda_runtime.h>
#include <math.h>
#include <stdint.h>

// ---------------- problem constants ----------------
constexpr int B_  = 8;
constexpr int NN  = 2000;
constexpr int E_  = 512;
constexpr int HEN = 1024;
constexpr int D_  = 128;   // 2*IB
constexpr int HD  = 512;
constexpr int KF  = 4096;  // P*HD
constexpr int IB_ = 64;
constexpr long long MR = (long long)B_ * NN; // 16000 rows

// ---------------- scratch layout ----------------
constexpr long long SZ_AG   = MR * E_;
constexpr long long SZ_HENC = MR * HEN;
constexpr long long SZ_H    = MR * D_;
constexpr long long SZ_GLW  = (long long)D_ * KF;
constexpr long long SZ_F    = MR * KF;
constexpr long long SZ_ATT  = (long long)B_ * NN * NN;
constexpr long long SZ_DINV = MR;
constexpr long long SZ_T    = MR * HD;
constexpr long long SZ_O    = MR * HD;
constexpr long long SZ_O3   = MR * D_;
constexpr long long SZ_Z    = (long long)B_ * IB_;

constexpr long long OFF_AG   = 0;
constexpr long long OFF_HENC = OFF_AG + SZ_AG;
constexpr long long OFF_H1   = OFF_HENC + SZ_HENC;
constexpr long long OFF_H2   = OFF_H1 + SZ_H;
constexpr long long OFF_GLW  = OFF_H2 + SZ_H;
constexpr long long OFF_F    = OFF_GLW + SZ_GLW;
constexpr long long OFF_ATT  = OFF_F + SZ_F;
constexpr long long OFF_DINV = OFF_ATT + SZ_ATT;
constexpr long long OFF_T    = OFF_DINV + SZ_DINV;
constexpr long long OFF_O1   = OFF_T + SZ_T;
constexpr long long OFF_O2   = OFF_O1 + SZ_O;
constexpr long long OFF_O3   = OFF_O2 + SZ_O;
constexpr long long OFF_Z    = OFF_O3 + SZ_O3;
constexpr long long SCRATCH_TOTAL = OFF_Z + SZ_Z;

__device__ float g_scratch[SCRATCH_TOTAL];

// ---------------- tf32 helpers ----------------
__device__ __forceinline__ uint32_t f2tf32(float v) {
    uint32_t r;
    asm("cvt.rna.tf32.f32 %0, %1;" : "=r"(r) : "f"(v));
    return r;
}

__device__ __forceinline__ void mma_tf32(float* c, const uint32_t* a, uint32_t b0, uint32_t b1) {
    asm volatile(
        "mma.sync.aligned.m16n8k8.row.col.f32.tf32.tf32.f32 "
        "{%0,%1,%2,%3}, {%4,%5,%6,%7}, {%8,%9}, {%0,%1,%2,%3};"
        : "+f"(c[0]), "+f"(c[1]), "+f"(c[2]), "+f"(c[3])
        : "r"(a[0]), "r"(a[1]), "r"(a[2]), "r"(a[3]), "r"(b0), "r"(b1));
}

// ---------------- tf32 tensor-core GEMM, double-buffered ----------------
// C[M,N] = act( epi( alpha * op(A) @ op(B) ) + bias )
// TA=0: A[m,k]. TA=1: A[k,m] -> A^T @ B.  TB=0: B[k,n]. TB=1: B[n,k] -> A @ B^T.
// ACT: 0 none, 1 relu, 2 gelu(exact)
// EPI: 0 none, 1: v = dinv[m]*v, 2: v = dinv[m]*(v + Tm[m,n]) + bias (GCN aggregate)
// SYM: gram symmetry — compute bm<=bn only, mirror-write off-diagonal tiles.
// Block: 128x128 tile, k-tile 16, 256 threads = 8 warps (4m x 2n), warp tile 32x64.
template<int TA, int TB, int ACT, int EPI, int SYM>
__global__ void __launch_bounds__(256, 2) tgemm_k(
    int M, int N, int K, float alpha,
    const float* __restrict__ A, int lda, long long sA,
    const float* __restrict__ B, int ldb, long long sB,
    float* __restrict__ C, int ldc, long long sC,
    const float* __restrict__ bias,
    const float* __restrict__ dinv, long long sD,
    const float* __restrict__ Tm, int ldt, long long sT)
{
    constexpr int PAD = 20;  // row stride in u32: conflict-free fragment LDS
    __shared__ uint32_t As[2][128 * PAD];
    __shared__ uint32_t Bs[2][128 * PAD];

    const int bz = blockIdx.z;
    A += bz * sA; B += bz * sB; C += bz * sC;
    if (EPI)      dinv += bz * sD;
    if (EPI == 2) Tm   += bz * sT;

    const int bn = blockIdx.x, bm = blockIdx.y;
    if (SYM && bm > bn) return;
    const int m0 = bm * 128, n0 = bn * 128;

    const int tid  = threadIdx.x;
    const int lane = tid & 31, warp = tid >> 5;
    const int g = lane >> 2, th = lane & 3;
    const int wm = (warp >> 1) * 32;
    const int wn = (warp & 1) * 64;

    float acc[2][8][4];
#pragma unroll
    for (int i = 0; i < 2; i++)
#pragma unroll
        for (int j = 0; j < 8; j++)
#pragma unroll
            for (int l = 0; l < 4; l++) acc[i][j][l] = 0.f;

    float ra[8], rb[8];
    const int KT = K >> 4;

    auto loadA = [&](int kt) {
#pragma unroll
        for (int it = 0; it < 2; it++) {
            int c = tid * 2 + it;
            if (TA == 0) {
                int row = c >> 2, kc = (c & 3) * 4;
                int gm = m0 + row;
                float4 v = make_float4(0.f, 0.f, 0.f, 0.f);
                if (gm < M) v = *reinterpret_cast<const float4*>(A + (long long)gm * lda + kt * 16 + kc);
                ra[it*4+0]=v.x; ra[it*4+1]=v.y; ra[it*4+2]=v.z; ra[it*4+3]=v.w;
            } else {
                int kr = c >> 5, mc = (c & 31) * 4;
                int gm = m0 + mc;
                float4 v = make_float4(0.f, 0.f, 0.f, 0.f);
                const float* src = A + (long long)(kt * 16 + kr) * lda + gm;
                if (gm + 3 < M) v = *reinterpret_cast<const float4*>(src);
                else { float t[4]={0,0,0,0}; for (int j=0;j<4;j++) if (gm+j<M) t[j]=src[j]; v=make_float4(t[0],t[1],t[2],t[3]); }
                ra[it*4+0]=v.x; ra[it*4+1]=v.y; ra[it*4+2]=v.z; ra[it*4+3]=v.w;
            }
        }
    };
    auto loadB = [&](int kt) {
#pragma unroll
        for (int it = 0; it < 2; it++) {
            int c = tid * 2 + it;
            if (TB == 1) {
                int row = c >> 2, kc = (c & 3) * 4;
                int gn = n0 + row;
                float4 v = make_float4(0.f, 0.f, 0.f, 0.f);
                if (gn < N) v = *reinterpret_cast<const float4*>(B + (long long)gn * ldb + kt * 16 + kc);
                rb[it*4+0]=v.x; rb[it*4+1]=v.y; rb[it*4+2]=v.z; rb[it*4+3]=v.w;
            } else {
                int kr = c >> 5, nc = (c & 31) * 4;
                int gn = n0 + nc;
                float4 v = make_float4(0.f, 0.f, 0.f, 0.f);
                const float* src = B + (long long)(kt * 16 + kr) * ldb + gn;
                if (gn + 3 < N) v = *reinterpret_cast<const float4*>(src);
                else { float t[4]={0,0,0,0}; for (int j=0;j<4;j++) if (gn+j<N) t[j]=src[j]; v=make_float4(t[0],t[1],t[2],t[3]); }
                rb[it*4+0]=v.x; rb[it*4+1]=v.y; rb[it*4+2]=v.z; rb[it*4+3]=v.w;
            }
        }
    };
    auto stsA = [&](int buf) {
        uint32_t* dst = As[buf];
#pragma unroll
        for (int it = 0; it < 2; it++) {
            int c = tid * 2 + it;
            if (TA == 0) {
                int row = c >> 2, kc = (c & 3) * 4;
#pragma unroll
                for (int j = 0; j < 4; j++) dst[row * PAD + kc + j] = f2tf32(ra[it*4+j]);
            } else {
                int kr = c >> 5, mc = (c & 31) * 4;
#pragma unroll
                for (int j = 0; j < 4; j++) dst[(mc + j) * PAD + kr] = f2tf32(ra[it*4+j]);
            }
        }
    };
    auto stsB = [&](int buf) {
        uint32_t* dst = Bs[buf];
#pragma unroll
        for (int it = 0; it < 2; it++) {
            int c = tid * 2 + it;
            if (TB == 1) {
                int row = c >> 2, kc = (c & 3) * 4;
#pragma unroll
                for (int j = 0; j < 4; j++) dst[row * PAD + kc + j] = f2tf32(rb[it*4+j]);
            } else {
                int kr = c >> 5, nc = (c & 31) * 4;
#pragma unroll
                for (int j = 0; j < 4; j++) dst[(nc + j) * PAD + kr] = f2tf32(rb[it*4+j]);
            }
        }
    };
    auto mmaTile = [&](int buf) {
        const uint32_t* Ab = As[buf];
        const uint32_t* Bb = Bs[buf];
#pragma unroll
        for (int s = 0; s < 2; s++) {
            const int k0 = s * 8;
            uint32_t a[2][4];
#pragma unroll
            for (int mt = 0; mt < 2; mt++) {
                int mrow = wm + mt * 16 + g;
                a[mt][0] = Ab[mrow * PAD + k0 + th];
                a[mt][1] = Ab[(mrow + 8) * PAD + k0 + th];
                a[mt][2] = Ab[mrow * PAD + k0 + th + 4];
                a[mt][3] = Ab[(mrow + 8) * PAD + k0 + th + 4];
            }
#pragma unroll
            for (int nt = 0; nt < 8; nt++) {
                int nrow = wn + nt * 8 + g;
                uint32_t b0 = Bb[nrow * PAD + k0 + th];
                uint32_t b1 = Bb[nrow * PAD + k0 + th + 4];
                mma_tf32(acc[0][nt], a[0], b0, b1);
                mma_tf32(acc[1][nt], a[1], b0, b1);
            }
        }
    };

    // ---- pipelined mainloop: 1 sync per k-tile ----
    loadA(0); loadB(0);
    stsA(0);  stsB(0);
    if (KT > 1) { loadA(1); loadB(1); }
    __syncthreads();
    for (int kt = 0; kt < KT; kt++) {
        int cur = kt & 1, nxt = cur ^ 1;
        if (kt + 1 < KT) { stsA(nxt); stsB(nxt); }     // store tile kt+1 (regs)
        if (kt + 2 < KT) { loadA(kt + 2); loadB(kt + 2); } // prefetch tile kt+2
        mmaTile(cur);
        __syncthreads();
    }

    // ---- epilogue ----
#pragma unroll
    for (int mt = 0; mt < 2; mt++) {
#pragma unroll
        for (int nt = 0; nt < 8; nt++) {
#pragma unroll
            for (int e = 0; e < 4; e++) {
                int gm = m0 + wm + mt * 16 + g + (e >= 2 ? 8 : 0);
                int gn = n0 + wn + nt * 8 + 2 * th + (e & 1);
                if (gm >= M || gn >= N) continue;
                float v = alpha * acc[mt][nt][e];
                if (EPI == 1) v = dinv[gm] * v;
                if (EPI == 2) v = dinv[gm] * (v + Tm[(long long)gm * ldt + gn]);
                if (bias)     v += bias[gn];
                if (ACT == 1) v = fmaxf(v, 0.f);
                if (ACT == 2) v = 0.5f * v * (1.f + erff(v * 0.70710678118654752f));
                C[(long long)gm * ldc + gn] = v;
                if (SYM && bm < bn) C[(long long)gn * ldc + gm] = v;
            }
        }
    }
}

// ---------------- A-matrix builder ----------------
__global__ void build_ag_k(const float* __restrict__ x, const float* __restrict__ emb,
                           const float* __restrict__ gw, const float* __restrict__ gb,
                           float* __restrict__ Ag)
{
    long long idx = (long long)blockIdx.x * blockDim.x + threadIdx.x;
    if (idx >= MR * E_) return;
    int e = (int)(idx & (E_ - 1));
    long long rn = idx >> 9;
    int n = (int)(rn % NN);
    float t = fmaf(x[rn], gw[e], gb[e]);
    float sgm = 1.0f / (1.0f + expf(-t));
    Ag[idx] = sgm * emb[(long long)n * E_ + e];
}

// ---------------- concat gl_w [P,D,HD] -> GLW [D, P*HD] ----------------
__global__ void build_glw_k(const float* __restrict__ glw, float* __restrict__ GLW)
{
    int idx = blockIdx.x * blockDim.x + threadIdx.x;
    if (idx >= D_ * KF) return;
    int k = idx / KF, c = idx % KF;
    int p = c >> 9, hh = c & 511;
    GLW[idx] = glw[((long long)p * D_ + k) * HD + hh];
}

// ---------------- top-k(50): byte-histogram radix select + masked softmax ----------------
__global__ void __launch_bounds__(256) topk_softmax_k(float* __restrict__ att)
{
    __shared__ float s[2000];
    __shared__ int   hist[256];
    __shared__ float wredf[8];
    __shared__ float s_bcast;
    __shared__ int   s_selb, s_selk;

    long long row = blockIdx.x;
    float* r = att + row * 2000;
    int tid = threadIdx.x;
    int lane = tid & 31, wid = tid >> 5;

    for (int i = tid; i < 2000; i += 256) s[i] = r[i];
    __syncthreads();

    // row max (values >= 0)
    float mx = 0.f;
    for (int i = tid; i < 2000; i += 256) mx = fmaxf(mx, s[i]);
#pragma unroll
    for (int o = 16; o; o >>= 1) mx = fmaxf(mx, __shfl_xor_sync(0xffffffffu, mx, o));
    if (lane == 0) wredf[wid] = mx;
    __syncthreads();
    if (tid == 0) { float m = wredf[0]; for (int w = 1; w < 8; w++) m = fmaxf(m, wredf[w]); s_bcast = m; }
    __syncthreads();
    mx = s_bcast;

    // 4-pass byte radix select for 50th-largest value bits (sign bit is 0)
    unsigned prefix = 0u;
    int k = 50;
#pragma unroll
    for (int pass = 0; pass < 4; pass++) {
        const int shift = 24 - 8 * pass;
        const unsigned hmask = (pass == 0) ? 0u : (0xFFFFFFFFu << (shift + 8));
        if (tid < 256) hist[tid] = 0;
        __syncthreads();
        for (int i = tid; i < 2000; i += 256) {
            unsigned u = __float_as_uint(s[i]);
            if ((u & hmask) == prefix)
                atomicAdd(&hist[(u >> shift) & 255], 1);
        }
        __syncthreads();
        if (tid == 0) {
            int acc = 0, b = 255;
            for (; b > 0; b--) { acc += hist[b]; if (acc >= k) break; }
            if (acc < k) acc += hist[0];   // b==0 fallthrough
            s_selb = b;
            s_selk = k - (acc - hist[b]);
        }
        __syncthreads();
        prefix |= ((unsigned)s_selb) << shift;
        k = s_selk;
        __syncthreads();
    }
    float thr = __uint_as_float(prefix);

    // masked softmax; masked entries exactly 0
    float sum = 0.f;
    for (int i = tid; i < 2000; i += 256) {
        float v = s[i];
        float e = (v >= thr) ? expf(v - mx) : 0.f;
        s[i] = e; sum += e;
    }
#pragma unroll
    for (int o = 16; o; o >>= 1) sum += __shfl_xor_sync(0xffffffffu, sum, o);
    if (lane == 0) wredf[wid] = sum;
    __syncthreads();
    if (tid == 0) { float t = 0.f; for (int w = 0; w < 8; w++) t += wredf[w]; s_bcast = t; }
    __syncthreads();
    float inv = 1.0f / s_bcast;
    for (int i = tid; i < 2000; i += 256) r[i] = s[i] * inv;
}

// ---------------- dinv[b,i] = 1/sqrt(1 + sum_j adj[b,j,i]) ----------------
__global__ void colsum_k(const float* __restrict__ adj, float* __restrict__ dinv)
{
    int b = blockIdx.y;
    int i = blockIdx.x * blockDim.x + threadIdx.x;
    if (i >= 2000) return;
    const float* p = adj + (long long)b * 2000 * 2000 + i;
    float s0 = 0.f, s1 = 0.f, s2 = 0.f, s3 = 0.f;
    for (int j = 0; j < 2000; j += 4) {
        s0 += p[(long long)j * 2000];
        s1 += p[(long long)(j + 1) * 2000];
        s2 += p[(long long)(j + 2) * 2000];
        s3 += p[(long long)(j + 3) * 2000];
    }
    float d = 1.0f + ((s0 + s1) + (s2 + s3));
    dinv[b * 2000 + i] = 1.0f / sqrtf(d);
}

// ---------------- mean over nodes; mu/std/z ----------------
__global__ void meanz_k(const float* __restrict__ O3, const float* __restrict__ eps,
                        float* __restrict__ mu, float* __restrict__ stdv, float* __restrict__ z)
{
    int b = blockIdx.x, d = threadIdx.x;
    const float* p = O3 + ((long long)b * 2000) * 128 + d;
    float s0 = 0.f, s1 = 0.f, s2 = 0.f, s3 = 0.f;
    for (int i = 0; i < 2000; i += 4) {
        s0 += p[(long long)i * 128];
        s1 += p[(long long)(i + 1) * 128];
        s2 += p[(long long)(i + 2) * 128];
        s3 += p[(long long)(i + 3) * 128];
    }
    __shared__ float sg[128];
    sg[d] = ((s0 + s1) + (s2 + s3)) / 2000.0f;
    __syncthreads();
    if (d < 64) {
        float m = sg[d];
        float sp = log1pf(expf(sg[64 + d] - 64.0f));
        mu[b * 64 + d] = m;
        stdv[b * 64 + d] = sp;
        z[b * 64 + d] = fmaf(eps[b * 64 + d], sp, m);
    }
}

// ---------------- decoder (grid: b x col-chunks of 250) ----------------
__global__ void __launch_bounds__(256) decode_k(
    const float* __restrict__ z, const float* __restrict__ w1, const float* __restrict__ b1,
    const float* __restrict__ gamma, const float* __restrict__ beta,
    const float* __restrict__ w2, const float* __restrict__ b2,
    float* __restrict__ xrec)
{
    __shared__ float h[1024];
    __shared__ float zs[64];
    int b = blockIdx.x, tid = threadIdx.x;
    if (tid < 64) zs[tid] = z[b * 64 + tid];
    __syncthreads();
    const float invc = 1.0f / sqrtf(1.0f + 1e-5f);
    for (int c = tid; c < 1024; c += 256) {
        float a = b1[c];
#pragma unroll 8
        for (int k = 0; k < 64; k++) a = fmaf(zs[k], w1[k * 1024 + c], a);
        a = a * (gamma[c] * invc) + beta[c];
        h[c] = fmaxf(a, 0.f);
    }
    __syncthreads();
    int c0 = blockIdx.y * 250;
    int c1 = min(c0 + 250, 2000);
    for (int c = c0 + tid; c < c1; c += 256) {
        float a = b2[c];
        for (int k = 0; k < 1024; k++) a = fmaf(h[k], w2[k * 2000 + c], a);
        xrec[b * 2000 + c] = fmaxf(a, 0.f);
    }
}

// ---------------- host orchestration ----------------
extern "C" void kernel_launch(void* const* d_in, const int* in_sizes, int n_in,
                              void* d_out, int out_size)
{
    const float* x1     = (const float*)d_in[0];
    const float* x2     = (const float*)d_in[1];
    const float* emb1   = (const float*)d_in[2];
    const float* gate_w = (const float*)d_in[3];
    const float* gate_b = (const float*)d_in[4];
    const float* enc_w1 = (const float*)d_in[5];
    const float* enc_b1 = (const float*)d_in[6];
    const float* enc_w2 = (const float*)d_in[7];
    const float* enc_b2 = (const float*)d_in[8];
    const float* gl_w   = (const float*)d_in[9];
    const float* g_w1   = (const float*)d_in[10];
    const float* g_b1   = (const float*)d_in[11];
    const float* g_w2   = (const float*)d_in[12];
    const float* g_b2   = (const float*)d_in[13];
    const float* g_w3   = (const float*)d_in[14];
    const float* g_b3   = (const float*)d_in[15];
    const float* dW1[2] = {(const float*)d_in[16], (const float*)d_in[22]};
    const float* dB1[2] = {(const float*)d_in[17], (const float*)d_in[23]};
    const float* dG [2] = {(const float*)d_in[18], (const float*)d_in[24]};
    const float* dBe[2] = {(const float*)d_in[19], (const float*)d_in[25]};
    const float* dW2[2] = {(const float*)d_in[20], (const float*)d_in[26]};
    const float* dB2[2] = {(const float*)d_in[21], (const float*)d_in[27]};
    const float* epsA[2]= {(const float*)d_in[28], (const float*)d_in[29]};

    float* sc = nullptr;
    cudaGetSymbolAddress((void**)&sc, g_scratch);
    float* Ag   = sc + OFF_AG;
    float* Henc = sc + OFF_HENC;
    float* Hbuf[2] = {sc + OFF_H1, sc + OFF_H2};
    float* GLW  = sc + OFF_GLW;
    float* F    = sc + OFF_F;
    float* att  = sc + OFF_ATT;
    float* dinv = sc + OFF_DINV;
    float* T    = sc + OFF_T;
    float* O1   = sc + OFF_O1;
    float* O2   = sc + OFF_O2;
    float* O3   = sc + OFF_O3;
    float* zb   = sc + OFF_Z;

    float* out = (float*)d_out;
    float* xrec[2] = {out,          out + 16000};
    float* muo [2] = {out + 32000,  out + 33024};
    float* stdo[2] = {out + 32512,  out + 33536};

    build_glw_k<<<(D_ * KF + 255) / 256, 256>>>(gl_w, GLW);

    // ---- encoders ----
    for (int xi = 0; xi < 2; xi++) {
        const float* x = xi ? x2 : x1;
        long long tot = MR * E_;
        build_ag_k<<<(unsigned)((tot + 255) / 256), 256>>>(x, emb1, gate_w, gate_b, Ag);
        tgemm_k<0,0,2,0,0><<<dim3(HEN / 128, 125, 1), 256>>>(
            16000, HEN, E_, 1.f, Ag, E_, 0, enc_w1, HEN, 0, Henc, HEN, 0,
            enc_b1, nullptr, 0, nullptr, 0, 0);
        tgemm_k<0,0,0,0,0><<<dim3(1, 125, 1), 256>>>(
            16000, D_, HEN, 1.f, Henc, HEN, 0, enc_w2, D_, 0, Hbuf[xi], D_, 0,
            enc_b2, nullptr, 0, nullptr, 0, 0);
    }

    // ---- per-view ----
    for (int xi = 0; xi < 2; xi++) {
        float* H = Hbuf[xi];
        // F = relu(H @ GLW)
        tgemm_k<0,0,1,0,0><<<dim3(KF / 128, 125, 1), 256>>>(
            16000, KF, D_, 1.f, H, D_, 0, GLW, KF, 0, F, KF, 0,
            nullptr, nullptr, 0, nullptr, 0, 0);
        // att[b] = F_b @ F_b^T / 8  (symmetric: compute upper tiles, mirror)
        tgemm_k<0,1,0,0,1><<<dim3(16, 16, 8), 256>>>(
            2000, 2000, KF, 0.125f,
            F, KF, (long long)2000 * KF,
            F, KF, (long long)2000 * KF,
            att, 2000, (long long)2000 * 2000,
            nullptr, nullptr, 0, nullptr, 0, 0);
        topk_softmax_k<<<16000, 256>>>(att);
        colsum_k<<<dim3(8, 8), 256>>>(att, dinv);

        // GCN layer 1
        tgemm_k<0,0,0,1,0><<<dim3(HD / 128, 125, 1), 256>>>(
            16000, HD, D_, 1.f, H, D_, 0, g_w1, HD, 0, T, HD, 0,
            nullptr, dinv, 0, nullptr, 0, 0);
        tgemm_k<1,0,1,2,0><<<dim3(HD / 128, 16, 8), 256>>>(
            2000, HD, 2000, 1.f,
            att, 2000, (long long)2000 * 2000,
            T, HD, (long long)2000 * HD,
            O1, HD, (long long)2000 * HD,
            g_b1, dinv, 2000, T, HD, (long long)2000 * HD);
        // layer 2
        tgemm_k<0,0,0,1,0><<<dim3(HD / 128, 125, 1), 256>>>(
            16000, HD, HD, 1.f, O1, HD, 0, g_w2, HD, 0, T, HD, 0,
            nullptr, dinv, 0, nullptr, 0, 0);
        tgemm_k<1,0,1,2,0><<<dim3(HD / 128, 16, 8), 256>>>(
            2000, HD, 2000, 1.f,
            att, 2000, (long long)2000 * 2000,
            T, HD, (long long)2000 * HD,
            O2, HD, (long long)2000 * HD,
            g_b2, dinv, 2000, T, HD, (long long)2000 * HD);
        // layer 3 (no relu)
        tgemm_k<0,0,0,1,0><<<dim3(1, 125, 1), 256>>>(
            16000, D_, HD, 1.f, O2, HD, 0, g_w3, D_, 0, T, D_, 0,
            nullptr, dinv, 0, nullptr, 0, 0);
        tgemm_k<1,0,0,2,0><<<dim3(1, 16, 8), 256>>>(
            2000, D_, 2000, 1.f,
            att, 2000, (long long)2000 * 2000,
            T, D_, (long long)2000 * D_,
            O3, D_, (long long)2000 * D_,
            g_b3, dinv, 2000, T, D_, (long long)2000 * D_);

        meanz_k<<<8, 128>>>(O3, epsA[xi], muo[xi], stdo[xi], zb);
        decode_k<<<dim3(8, 8), 256>>>(zb, dW1[xi], dB1[xi], dG[xi], dBe[xi], dW2[xi], dB2[xi], xrec[xi]);
    }
}